// round 12
// baseline (speedup 1.0000x reference)
#include <cuda_runtime.h>
#include <cuda_fp16.h>
#include <math.h>

#define NU 50000
#define NI 100000
#define NN 150000
#define D  64
#define NINT 128
#define NE 3000000
#define NL 2
#define SCAN_TB 256
#define NBLK ((NN + SCAN_TB - 1) / SCAN_TB)   // 586

// ---------------- scratch (device globals) ----------------------------------
__device__ __align__(256) float d_embA[NN * D];
__device__ __align__(256) float d_embB[NN * D];
__device__ __align__(256) float d_gnn[NN * D];
__device__ __align__(256) float d_int[NN * D];
__device__ __align__(256) float d_scaled[NN * D];   // dis[n] * emb[n]
// packed normalized rows, fp16: chunk q (16B) = { g[4q..4q+3], i[4q..4q+3] }
__device__ __align__(256) __half d_nrm[NN * 2 * D];
__device__ __align__(256) float d_dis[NN];
__device__ __align__(256) int   d_cnt[NN];
__device__ __align__(256) int   d_rowptr[NN + 1];
__device__ __align__(256) int   d_fill[NN];
__device__ __align__(256) int   d_csr_t[NE];
__device__ __align__(256) int   d_blksum[NBLK];

__device__ __forceinline__ float2 u2f2(unsigned u) {
    return __half22float2(*(__half2*)&u);
}

// ---------------------------------------------------------------------------
__global__ void k_init(const float* __restrict__ ue, const float* __restrict__ ie,
                       float* __restrict__ out) {
    int i = blockIdx.x * blockDim.x + threadIdx.x;
    const int n4  = NN * D / 4;
    const int nu4 = NU * D / 4;
    if (i >= n4) return;
    float4 v = (i < nu4) ? ((const float4*)ue)[i] : ((const float4*)ie)[i - nu4];
    ((float4*)d_embA)[i] = v;
    __stcs((float4*)out + i, v);
}

__global__ void k_cnt_zero() {
    int i = blockIdx.x * blockDim.x + threadIdx.x;
    if (i < NN) d_cnt[i] = 0;
}

__global__ void k_cnt(const int* __restrict__ h) {
    int e = blockIdx.x * blockDim.x + threadIdx.x;
    if (e < NE) atomicAdd(&d_cnt[__ldcs(&h[e])], 1.0f == 1.0f ? 1 : 1);
}

__global__ void k_blocksum() {
    __shared__ int sh[SCAN_TB];
    int i = blockIdx.x * SCAN_TB + threadIdx.x;
    int v = (i < NN) ? d_cnt[i] : 0;
    sh[threadIdx.x] = v;
    __syncthreads();
    for (int off = SCAN_TB / 2; off > 0; off >>= 1) {
        if (threadIdx.x < off) sh[threadIdx.x] += sh[threadIdx.x + off];
        __syncthreads();
    }
    if (threadIdx.x == 0) d_blksum[blockIdx.x] = sh[0];
}

__global__ void k_scanblk() {
    __shared__ int sh[1024];
    int tid = threadIdx.x;
    sh[tid] = (tid < NBLK) ? d_blksum[tid] : 0;
    __syncthreads();
    for (int off = 1; off < 1024; off <<= 1) {
        int v = (tid >= off) ? sh[tid - off] : 0;
        __syncthreads();
        sh[tid] += v;
        __syncthreads();
    }
    if (tid < NBLK) d_blksum[tid] = (tid > 0) ? sh[tid - 1] : 0;
    if (tid == 0) d_rowptr[NN] = sh[1023];
}

__global__ void k_rowptr() {
    __shared__ int sh[SCAN_TB];
    int i = blockIdx.x * SCAN_TB + threadIdx.x;
    int c = (i < NN) ? d_cnt[i] : 0;
    sh[threadIdx.x] = c;
    __syncthreads();
    for (int off = 1; off < SCAN_TB; off <<= 1) {
        int v = (threadIdx.x >= off) ? sh[threadIdx.x - off] : 0;
        __syncthreads();
        sh[threadIdx.x] += v;
        __syncthreads();
    }
    if (i < NN) {
        int excl = sh[threadIdx.x] - c + d_blksum[blockIdx.x];
        d_rowptr[i] = excl;
        d_dis[i]  = (c > 0) ? rsqrtf((float)c) : 0.0f;
        d_fill[i] = 0;
    }
}

__global__ void k_csr(const int* __restrict__ h, const int* __restrict__ t) {
    int e = blockIdx.x * blockDim.x + threadIdx.x;
    if (e >= NE) return;
    int hh = __ldcs(&h[e]);
    int pos = d_rowptr[hh] + atomicAdd(&d_fill[hh], 1);
    d_csr_t[pos] = __ldcs(&t[e]);
}

// d_scaled = dis[n] * embA  (initial layer)
__global__ void k_scale0() {
    int i = blockIdx.x * blockDim.x + threadIdx.x;
    const int n4 = NN * D / 4;
    if (i >= n4) return;
    float s = d_dis[i >> 4];
    float4 v = ((const float4*)d_embA)[i];
    v.x *= s; v.y *= s; v.z *= s; v.w *= s;
    ((float4*)d_scaled)[i] = v;
}

// warp per node, 16 lanes/edge, 2 edges per half-iter (4 edges in flight).
// gnn[n] = dis[n] * sum_t scaled[t] ; writes f32 row (stream) + fp16 norm g-part.
__global__ void k_spmm_gnn() {
    int n = (blockIdx.x * blockDim.x + threadIdx.x) >> 5;
    int lane = threadIdx.x & 31;
    if (n >= NN) return;
    int half = lane >> 4;
    int q    = lane & 15;
    float dh = d_dis[n];
    float4 a0 = make_float4(0.f, 0.f, 0.f, 0.f);
    float4 a1 = make_float4(0.f, 0.f, 0.f, 0.f);
    int b = d_rowptr[n], e = d_rowptr[n + 1];
    int i = b + half;
    for (; i + 2 < e; i += 4) {
        int t0 = __ldcs(&d_csr_t[i]);
        int t1 = __ldcs(&d_csr_t[i + 2]);
        float4 r0 = __ldg((const float4*)(d_scaled + t0 * D) + q);
        float4 r1 = __ldg((const float4*)(d_scaled + t1 * D) + q);
        a0.x += r0.x; a0.y += r0.y; a0.z += r0.z; a0.w += r0.w;
        a1.x += r1.x; a1.y += r1.y; a1.z += r1.z; a1.w += r1.w;
    }
    for (; i < e; i += 2) {
        int t0 = __ldcs(&d_csr_t[i]);
        float4 r0 = __ldg((const float4*)(d_scaled + t0 * D) + q);
        a0.x += r0.x; a0.y += r0.y; a0.z += r0.z; a0.w += r0.w;
    }
    a0.x = dh * (a0.x + a1.x); a0.y = dh * (a0.y + a1.y);
    a0.z = dh * (a0.z + a1.z); a0.w = dh * (a0.w + a1.w);
    a0.x += __shfl_xor_sync(0xffffffffu, a0.x, 16);
    a0.y += __shfl_xor_sync(0xffffffffu, a0.y, 16);
    a0.z += __shfl_xor_sync(0xffffffffu, a0.z, 16);
    a0.w += __shfl_xor_sync(0xffffffffu, a0.w, 16);
    float sg = a0.x * a0.x + a0.y * a0.y + a0.z * a0.z + a0.w * a0.w;
    #pragma unroll
    for (int o = 8; o >= 1; o >>= 1) sg += __shfl_xor_sync(0xffffffffu, sg, o);
    float s = 1.0f / fmaxf(sqrtf(sg), 1e-8f);
    if (half == 0) {
        __stcs((float4*)(d_gnn + n * D) + q, a0);   // single-use downstream
        __half2 p0 = __floats2half2_rn(a0.x * s, a0.y * s);
        __half2 p1 = __floats2half2_rn(a0.z * s, a0.w * s);
        uint2 u;
        u.x = *(unsigned*)&p0;
        u.y = *(unsigned*)&p1;
        *(uint2*)(d_nrm + n * 2 * D + 8 * q) = u;   // hot next kernel: keep cached
    }
}

// warp-per-row softmax-intent projection; writes f32 row (stream) + fp16 norm i-part.
__global__ void k_intent(const float* __restrict__ cur,
                         const float* __restrict__ uW, const float* __restrict__ iW) {
    __shared__ float WT[NINT][D + 1];
    __shared__ float rowbuf[8][D];
    int wid = threadIdx.x >> 5, lane = threadIdx.x & 31;
    int row0 = blockIdx.x * 8;
    const float* W = (row0 < NU) ? uW : iW;
    for (int idx = threadIdx.x; idx < D * NINT; idx += blockDim.x) {
        int dd = idx / NINT, j = idx % NINT;
        WT[j][dd] = W[idx];
    }
    __syncthreads();
    int row = row0 + wid;
    if (row >= NN) return;
    const float* src = cur + row * D;
    rowbuf[wid][lane]      = src[lane];
    rowbuf[wid][lane + 32] = src[lane + 32];
    __syncwarp();

    float lg[4] = {0.f, 0.f, 0.f, 0.f};
    #pragma unroll
    for (int dd = 0; dd < D; dd++) {
        float rb = rowbuf[wid][dd];
        #pragma unroll
        for (int s = 0; s < 4; s++) lg[s] += rb * WT[s * 32 + lane][dd];
    }
    float m = fmaxf(fmaxf(lg[0], lg[1]), fmaxf(lg[2], lg[3]));
    #pragma unroll
    for (int o = 16; o >= 1; o >>= 1) m = fmaxf(m, __shfl_xor_sync(0xffffffffu, m, o));
    float p[4], ssum = 0.f;
    #pragma unroll
    for (int s = 0; s < 4; s++) { p[s] = expf(lg[s] - m); ssum += p[s]; }
    #pragma unroll
    for (int o = 16; o >= 1; o >>= 1) ssum += __shfl_xor_sync(0xffffffffu, ssum, o);
    float inv = 1.0f / ssum;
    #pragma unroll
    for (int s = 0; s < 4; s++) p[s] *= inv;

    float o0 = 0.f, o1 = 0.f;
    #pragma unroll
    for (int s = 0; s < 4; s++) {
        #pragma unroll
        for (int l = 0; l < 32; l++) {
            float pv = __shfl_sync(0xffffffffu, p[s], l);
            int j = s * 32 + l;
            o0 += pv * WT[j][lane];
            o1 += pv * WT[j][lane + 32];
        }
    }
    __stcs(&d_int[row * D + lane], o0);          // single-use downstream
    __stcs(&d_int[row * D + lane + 32], o1);
    float si = o0 * o0 + o1 * o1;
    #pragma unroll
    for (int o = 16; o >= 1; o >>= 1) si += __shfl_xor_sync(0xffffffffu, si, o);
    si = __shfl_sync(0xffffffffu, si, 0);
    float s = 1.0f / fmaxf(sqrtf(si), 1e-8f);
    // i-part of packed nrm: dim d -> index 8*(d/4) + 4 + (d%4)  (hot: cached)
    int d0 = lane, d1 = lane + 32;
    d_nrm[row * 2 * D + 8 * (d0 >> 2) + 4 + (d0 & 3)] = __float2half_rn(o0 * s);
    d_nrm[row * 2 * D + 8 * (d1 >> 2) + 4 + (d1 & 3)] = __float2half_rn(o1 * s);
}

// fused adaptive pass, warp per node, 16 lanes/edge, unrolled 2x per half.
// Gather-hot arrays (nrm, cur) default-cached; single-use traffic streamed.
__global__ void k_adaptive(const float* __restrict__ cur, float* __restrict__ newe,
                           float* __restrict__ out) {
    int n = (blockIdx.x * blockDim.x + threadIdx.x) >> 5;
    int lane = threadIdx.x & 31;
    if (n >= NN) return;
    int half = lane >> 4;
    int q    = lane & 15;
    unsigned hmask = half ? 0xFFFF0000u : 0x0000FFFFu;
    int b = d_rowptr[n], e = d_rowptr[n + 1];

    // h-side normalized chunk
    uint4 hv = __ldg((const uint4*)(d_nrm + n * 2 * D) + q);
    float2 gh01 = u2f2(hv.x);
    float2 gh23 = u2f2(hv.y);
    float2 ih01 = u2f2(hv.z);
    float2 ih23 = u2f2(hv.w);

    float rsg = 0.f, rsi = 0.f;
    float4 accg = make_float4(0.f, 0.f, 0.f, 0.f);
    float4 acci = make_float4(0.f, 0.f, 0.f, 0.f);

    int i = b + half;
    for (; i + 2 < e; i += 4) {
        int t0 = __ldcs(&d_csr_t[i]);
        int t1 = __ldcs(&d_csr_t[i + 2]);
        uint4 v0 = __ldg((const uint4*)(d_nrm + t0 * 2 * D) + q);
        uint4 v1 = __ldg((const uint4*)(d_nrm + t1 * 2 * D) + q);
        float4 ev0 = __ldg((const float4*)(cur + t0 * D) + q);
        float4 ev1 = __ldg((const float4*)(cur + t1 * D) + q);

        float2 a, c;
        a = u2f2(v0.x); c = u2f2(v0.y);
        float g0 = gh01.x * a.x + gh01.y * a.y + gh23.x * c.x + gh23.y * c.y;
        a = u2f2(v0.z); c = u2f2(v0.w);
        float i0 = ih01.x * a.x + ih01.y * a.y + ih23.x * c.x + ih23.y * c.y;
        a = u2f2(v1.x); c = u2f2(v1.y);
        float g1 = gh01.x * a.x + gh01.y * a.y + gh23.x * c.x + gh23.y * c.y;
        a = u2f2(v1.z); c = u2f2(v1.w);
        float i1 = ih01.x * a.x + ih01.y * a.y + ih23.x * c.x + ih23.y * c.y;

        #pragma unroll
        for (int o = 8; o >= 1; o >>= 1) {
            g0 += __shfl_xor_sync(hmask, g0, o);
            i0 += __shfl_xor_sync(hmask, i0, o);
            g1 += __shfl_xor_sync(hmask, g1, o);
            i1 += __shfl_xor_sync(hmask, i1, o);
        }
        float ag0 = (g0 + 1.0f) * 0.5f;
        float ai0 = (i0 + 1.0f) * 0.5f;
        float ag1 = (g1 + 1.0f) * 0.5f;
        float ai1 = (i1 + 1.0f) * 0.5f;
        rsg += ag0 + ag1;
        rsi += ai0 + ai1;
        accg.x += ag0 * ev0.x + ag1 * ev1.x;
        accg.y += ag0 * ev0.y + ag1 * ev1.y;
        accg.z += ag0 * ev0.z + ag1 * ev1.z;
        accg.w += ag0 * ev0.w + ag1 * ev1.w;
        acci.x += ai0 * ev0.x + ai1 * ev1.x;
        acci.y += ai0 * ev0.y + ai1 * ev1.y;
        acci.z += ai0 * ev0.z + ai1 * ev1.z;
        acci.w += ai0 * ev0.w + ai1 * ev1.w;
    }
    for (; i < e; i += 2) {
        int t0 = __ldcs(&d_csr_t[i]);
        uint4 v0 = __ldg((const uint4*)(d_nrm + t0 * 2 * D) + q);
        float4 ev0 = __ldg((const float4*)(cur + t0 * D) + q);
        float2 a, c;
        a = u2f2(v0.x); c = u2f2(v0.y);
        float g0 = gh01.x * a.x + gh01.y * a.y + gh23.x * c.x + gh23.y * c.y;
        a = u2f2(v0.z); c = u2f2(v0.w);
        float i0 = ih01.x * a.x + ih01.y * a.y + ih23.x * c.x + ih23.y * c.y;
        #pragma unroll
        for (int o = 8; o >= 1; o >>= 1) {
            g0 += __shfl_xor_sync(hmask, g0, o);
            i0 += __shfl_xor_sync(hmask, i0, o);
        }
        float ag0 = (g0 + 1.0f) * 0.5f;
        float ai0 = (i0 + 1.0f) * 0.5f;
        rsg += ag0;
        rsi += ai0;
        accg.x += ag0 * ev0.x; accg.y += ag0 * ev0.y;
        accg.z += ag0 * ev0.z; accg.w += ag0 * ev0.w;
        acci.x += ai0 * ev0.x; acci.y += ai0 * ev0.y;
        acci.z += ai0 * ev0.z; acci.w += ai0 * ev0.w;
    }

    // combine halves (warp reconverged)
    rsg += __shfl_xor_sync(0xffffffffu, rsg, 16);
    rsi += __shfl_xor_sync(0xffffffffu, rsi, 16);
    accg.x += __shfl_xor_sync(0xffffffffu, accg.x, 16);
    accg.y += __shfl_xor_sync(0xffffffffu, accg.y, 16);
    accg.z += __shfl_xor_sync(0xffffffffu, accg.z, 16);
    accg.w += __shfl_xor_sync(0xffffffffu, accg.w, 16);
    acci.x += __shfl_xor_sync(0xffffffffu, acci.x, 16);
    acci.y += __shfl_xor_sync(0xffffffffu, acci.y, 16);
    acci.z += __shfl_xor_sync(0xffffffffu, acci.z, 16);
    acci.w += __shfl_xor_sync(0xffffffffu, acci.w, 16);

    float dg = (rsg > 0.f) ? (1.0f / rsg) : 0.f;
    float di = (rsi > 0.f) ? (1.0f / rsi) : 0.f;

    if (half == 0) {
        float4 gh4 = __ldcs((const float4*)(d_gnn + n * D) + q);   // single-use
        float4 ih4 = __ldcs((const float4*)(d_int + n * D) + q);   // single-use
        float4 e0  = __ldg((const float4*)(cur   + n * D) + q);    // hot array
        float4 nv;
        nv.x = gh4.x + ih4.x + dg * accg.x + di * acci.x + e0.x;
        nv.y = gh4.y + ih4.y + dg * accg.y + di * acci.y + e0.y;
        nv.z = gh4.z + ih4.z + dg * accg.z + di * acci.z + e0.z;
        nv.w = gh4.w + ih4.w + dg * accg.w + di * acci.w + e0.w;
        ((float4*)(newe + n * D))[q] = nv;                         // hot next layer
        float4 ov = __ldcs((const float4*)(out + n * D) + q);      // single-use
        ov.x += nv.x; ov.y += nv.y; ov.z += nv.z; ov.w += nv.w;
        __stcs((float4*)(out + n * D) + q, ov);                    // single-use
        // pre-scaled embedding for next layer's gnn SpMM (hot next kernel)
        float ds = d_dis[n];
        float4 sv = make_float4(ds * nv.x, ds * nv.y, ds * nv.z, ds * nv.w);
        ((float4*)(d_scaled + n * D))[q] = sv;
    }
}

// ---------------------------------------------------------------------------
extern "C" void kernel_launch(void* const* d_in, const int* in_sizes, int n_in,
                              void* d_out, int out_size) {
    const float* ue = (const float*)d_in[0];
    const float* ie = (const float*)d_in[1];
    const float* uW = (const float*)d_in[2];
    const float* iW = (const float*)d_in[3];
    const int*   h  = (const int*)d_in[4];
    const int*   t  = (const int*)d_in[5];
    float* out = (float*)d_out;

    const int TB = 256;
    const int n4   = NN * D / 4;
    const int gN4  = (n4 + TB - 1) / TB;
    const int gNN  = (NN + TB - 1) / TB;
    const int gE   = (NE + TB - 1) / TB;
    const int gNW  = (NN * 32 + TB - 1) / TB;   // warp-per-node

    float *embA, *embB;
    cudaGetSymbolAddress((void**)&embA, d_embA);
    cudaGetSymbolAddress((void**)&embB, d_embB);

    k_init<<<gN4, TB>>>(ue, ie, out);
    k_cnt_zero<<<gNN, TB>>>();
    k_cnt<<<gE, TB>>>(h);
    k_blocksum<<<NBLK, SCAN_TB>>>();
    k_scanblk<<<1, 1024>>>();
    k_rowptr<<<NBLK, SCAN_TB>>>();
    k_csr<<<gE, TB>>>(h, t);
    k_scale0<<<gN4, TB>>>();

    float* cur = embA;
    float* nxt = embB;
    for (int layer = 0; layer < NL; layer++) {
        k_spmm_gnn<<<gNW, TB>>>();
        k_intent<<<NN / 8, TB>>>(cur, uW, iW);
        k_adaptive<<<gNW, TB>>>(cur, nxt, out);
        float* tmp = cur; cur = nxt; nxt = tmp;
    }
}

// round 13
// speedup vs baseline: 1.1429x; 1.1429x over previous
#include <cuda_runtime.h>
#include <cuda_fp16.h>
#include <math.h>

#define NU 50000
#define NI 100000
#define NN 150000
#define D  64
#define NINT 128
#define NE 3000000
#define NL 2
#define SCAN_TB 256
#define NBLK ((NN + SCAN_TB - 1) / SCAN_TB)   // 586

// alpha scale: dot_int/(127*127) -> alpha = (dot+1)/2 = dot_int*K + 0.5
#define KQ (0.5f / 16129.0f)

// ---------------- scratch (device globals) ----------------------------------
__device__ __align__(256) float d_embA[NN * D];
__device__ __align__(256) float d_embB[NN * D];
__device__ __align__(256) float d_gnn[NN * D];
__device__ __align__(256) float d_int[NN * D];
__device__ __align__(256) float d_scaled[NN * D];    // dis[n] * emb[n] (f32)
__device__ __align__(256) __half d_embHA[NN * D];    // fp16 emb shadow (dbl-buffered)
__device__ __align__(256) __half d_embHB[NN * D];
// int8 packed normalized rows: 128B/node; chunk q (8B) = { g[4q..4q+3], i[4q..4q+3] }
__device__ __align__(256) char d_nrm8[NN * 2 * D];
__device__ __align__(256) float d_dis[NN];
__device__ __align__(256) int   d_cnt[NN];
__device__ __align__(256) int   d_rowptr[NN + 1];
__device__ __align__(256) int   d_fill[NN];
__device__ __align__(256) int   d_csr_t[NE];
__device__ __align__(256) int   d_blksum[NBLK];

__device__ __forceinline__ float2 u2f2(unsigned u) {
    return __half22float2(*(__half2*)&u);
}
__device__ __forceinline__ unsigned pack_q127(float a, float b, float c, float d, float s) {
    int b0 = max(-127, min(127, __float2int_rn(a * s)));
    int b1 = max(-127, min(127, __float2int_rn(b * s)));
    int b2 = max(-127, min(127, __float2int_rn(c * s)));
    int b3 = max(-127, min(127, __float2int_rn(d * s)));
    return (unsigned)(b0 & 0xFF) | ((unsigned)(b1 & 0xFF) << 8) |
           ((unsigned)(b2 & 0xFF) << 16) | ((unsigned)(b3 & 0xFF) << 24);
}

// ---------------------------------------------------------------------------
__global__ void k_init(const float* __restrict__ ue, const float* __restrict__ ie,
                       float* __restrict__ out) {
    int i = blockIdx.x * blockDim.x + threadIdx.x;
    const int n4  = NN * D / 4;
    const int nu4 = NU * D / 4;
    if (i >= n4) return;
    float4 v = (i < nu4) ? ((const float4*)ue)[i] : ((const float4*)ie)[i - nu4];
    ((float4*)d_embA)[i] = v;
    ((float4*)out)[i]    = v;
}

__global__ void k_cnt_zero() {
    int i = blockIdx.x * blockDim.x + threadIdx.x;
    if (i < NN) d_cnt[i] = 0;
}

__global__ void k_cnt(const int* __restrict__ h) {
    int e = blockIdx.x * blockDim.x + threadIdx.x;
    if (e < NE) atomicAdd(&d_cnt[h[e]], 1);
}

__global__ void k_blocksum() {
    __shared__ int sh[SCAN_TB];
    int i = blockIdx.x * SCAN_TB + threadIdx.x;
    int v = (i < NN) ? d_cnt[i] : 0;
    sh[threadIdx.x] = v;
    __syncthreads();
    for (int off = SCAN_TB / 2; off > 0; off >>= 1) {
        if (threadIdx.x < off) sh[threadIdx.x] += sh[threadIdx.x + off];
        __syncthreads();
    }
    if (threadIdx.x == 0) d_blksum[blockIdx.x] = sh[0];
}

__global__ void k_scanblk() {
    __shared__ int sh[1024];
    int tid = threadIdx.x;
    sh[tid] = (tid < NBLK) ? d_blksum[tid] : 0;
    __syncthreads();
    for (int off = 1; off < 1024; off <<= 1) {
        int v = (tid >= off) ? sh[tid - off] : 0;
        __syncthreads();
        sh[tid] += v;
        __syncthreads();
    }
    if (tid < NBLK) d_blksum[tid] = (tid > 0) ? sh[tid - 1] : 0;
    if (tid == 0) d_rowptr[NN] = sh[1023];
}

__global__ void k_rowptr() {
    __shared__ int sh[SCAN_TB];
    int i = blockIdx.x * SCAN_TB + threadIdx.x;
    int c = (i < NN) ? d_cnt[i] : 0;
    sh[threadIdx.x] = c;
    __syncthreads();
    for (int off = 1; off < SCAN_TB; off <<= 1) {
        int v = (threadIdx.x >= off) ? sh[threadIdx.x - off] : 0;
        __syncthreads();
        sh[threadIdx.x] += v;
        __syncthreads();
    }
    if (i < NN) {
        int excl = sh[threadIdx.x] - c + d_blksum[blockIdx.x];
        d_rowptr[i] = excl;
        d_dis[i]  = (c > 0) ? rsqrtf((float)c) : 0.0f;
        d_fill[i] = 0;
    }
}

__global__ void k_csr(const int* __restrict__ h, const int* __restrict__ t) {
    int e = blockIdx.x * blockDim.x + threadIdx.x;
    if (e >= NE) return;
    int hh = h[e];
    int pos = d_rowptr[hh] + atomicAdd(&d_fill[hh], 1);
    d_csr_t[pos] = t[e];
}

// scaled = dis[n]*embA (f32), embHA = fp16(embA)  (layer-0 shadows)
__global__ void k_scale0() {
    int i = blockIdx.x * blockDim.x + threadIdx.x;
    const int n4 = NN * D / 4;
    if (i >= n4) return;
    float s = d_dis[i >> 4];
    float4 v = ((const float4*)d_embA)[i];
    __half2 h0 = __floats2half2_rn(v.x, v.y);
    __half2 h1 = __floats2half2_rn(v.z, v.w);
    uint2 ue_;
    ue_.x = *(unsigned*)&h0; ue_.y = *(unsigned*)&h1;
    ((uint2*)d_embHA)[i] = ue_;
    v.x *= s; v.y *= s; v.z *= s; v.w *= s;
    ((float4*)d_scaled)[i] = v;
}

// warp per node, 16 lanes/edge, 2 edges per half-iter (4 edges in flight).
// gnn[n] = dis[n] * sum_t scaled[t] ; writes f32 row + int8 normalized g-part.
__global__ void k_spmm_gnn() {
    int n = (blockIdx.x * blockDim.x + threadIdx.x) >> 5;
    int lane = threadIdx.x & 31;
    if (n >= NN) return;
    int half = lane >> 4;
    int q    = lane & 15;
    float dh = d_dis[n];
    float4 a0 = make_float4(0.f, 0.f, 0.f, 0.f);
    float4 a1 = make_float4(0.f, 0.f, 0.f, 0.f);
    int b = d_rowptr[n], e = d_rowptr[n + 1];
    int i = b + half;
    for (; i + 2 < e; i += 4) {
        int t0 = __ldg(&d_csr_t[i]);
        int t1 = __ldg(&d_csr_t[i + 2]);
        float4 r0 = __ldg((const float4*)(d_scaled + t0 * D) + q);
        float4 r1 = __ldg((const float4*)(d_scaled + t1 * D) + q);
        a0.x += r0.x; a0.y += r0.y; a0.z += r0.z; a0.w += r0.w;
        a1.x += r1.x; a1.y += r1.y; a1.z += r1.z; a1.w += r1.w;
    }
    for (; i < e; i += 2) {
        int t0 = __ldg(&d_csr_t[i]);
        float4 r0 = __ldg((const float4*)(d_scaled + t0 * D) + q);
        a0.x += r0.x; a0.y += r0.y; a0.z += r0.z; a0.w += r0.w;
    }
    a0.x = dh * (a0.x + a1.x); a0.y = dh * (a0.y + a1.y);
    a0.z = dh * (a0.z + a1.z); a0.w = dh * (a0.w + a1.w);
    a0.x += __shfl_xor_sync(0xffffffffu, a0.x, 16);
    a0.y += __shfl_xor_sync(0xffffffffu, a0.y, 16);
    a0.z += __shfl_xor_sync(0xffffffffu, a0.z, 16);
    a0.w += __shfl_xor_sync(0xffffffffu, a0.w, 16);
    float sg = a0.x * a0.x + a0.y * a0.y + a0.z * a0.z + a0.w * a0.w;
    #pragma unroll
    for (int o = 8; o >= 1; o >>= 1) sg += __shfl_xor_sync(0xffffffffu, sg, o);
    float s = 127.0f / fmaxf(sqrtf(sg), 1e-8f);
    if (half == 0) {
        ((float4*)(d_gnn + n * D))[q] = a0;
        // int8 g-part of chunk q (4 bytes at row offset 8q)
        unsigned p = pack_q127(a0.x, a0.y, a0.z, a0.w, s);
        *(unsigned*)(d_nrm8 + n * 2 * D + 8 * q) = p;
    }
}

// warp-per-row softmax-intent projection; writes f32 row + int8 normalized i-part.
__global__ void k_intent(const float* __restrict__ cur,
                         const float* __restrict__ uW, const float* __restrict__ iW) {
    __shared__ float WT[NINT][D + 1];
    __shared__ float rowbuf[8][D];
    int wid = threadIdx.x >> 5, lane = threadIdx.x & 31;
    int row0 = blockIdx.x * 8;
    const float* W = (row0 < NU) ? uW : iW;
    for (int idx = threadIdx.x; idx < D * NINT; idx += blockDim.x) {
        int dd = idx / NINT, j = idx % NINT;
        WT[j][dd] = W[idx];
    }
    __syncthreads();
    int row = row0 + wid;
    if (row >= NN) return;
    const float* src = cur + row * D;
    rowbuf[wid][lane]      = src[lane];
    rowbuf[wid][lane + 32] = src[lane + 32];
    __syncwarp();

    float lg[4] = {0.f, 0.f, 0.f, 0.f};
    #pragma unroll
    for (int dd = 0; dd < D; dd++) {
        float rb = rowbuf[wid][dd];
        #pragma unroll
        for (int s = 0; s < 4; s++) lg[s] += rb * WT[s * 32 + lane][dd];
    }
    float m = fmaxf(fmaxf(lg[0], lg[1]), fmaxf(lg[2], lg[3]));
    #pragma unroll
    for (int o = 16; o >= 1; o >>= 1) m = fmaxf(m, __shfl_xor_sync(0xffffffffu, m, o));
    float p[4], ssum = 0.f;
    #pragma unroll
    for (int s = 0; s < 4; s++) { p[s] = expf(lg[s] - m); ssum += p[s]; }
    #pragma unroll
    for (int o = 16; o >= 1; o >>= 1) ssum += __shfl_xor_sync(0xffffffffu, ssum, o);
    float inv = 1.0f / ssum;
    #pragma unroll
    for (int s = 0; s < 4; s++) p[s] *= inv;

    float o0 = 0.f, o1 = 0.f;
    #pragma unroll
    for (int s = 0; s < 4; s++) {
        #pragma unroll
        for (int l = 0; l < 32; l++) {
            float pv = __shfl_sync(0xffffffffu, p[s], l);
            int j = s * 32 + l;
            o0 += pv * WT[j][lane];
            o1 += pv * WT[j][lane + 32];
        }
    }
    d_int[row * D + lane]      = o0;
    d_int[row * D + lane + 32] = o1;
    float si = o0 * o0 + o1 * o1;
    #pragma unroll
    for (int o = 16; o >= 1; o >>= 1) si += __shfl_xor_sync(0xffffffffu, si, o);
    float s = 127.0f / fmaxf(sqrtf(si), 1e-8f);
    // int8 i-part: dim d -> byte n*128 + 8*(d/4) + 4 + (d%4)
    int d0 = lane, d1 = lane + 32;
    int q0 = max(-127, min(127, __float2int_rn(o0 * s)));
    int q1 = max(-127, min(127, __float2int_rn(o1 * s)));
    d_nrm8[row * 2 * D + 8 * (d0 >> 2) + 4 + (d0 & 3)] = (char)q0;
    d_nrm8[row * 2 * D + 8 * (d1 >> 2) + 4 + (d1 & 3)] = (char)q1;
}

// fused adaptive pass, warp per node, 16 lanes/edge, unrolled 2x per half.
// Per edge-lane: ONE 8B int8 load (both dots via dp4a) + ONE 8B fp16 emb load.
__global__ void k_adaptive(const float* __restrict__ cur,
                           const __half* __restrict__ curH,
                           float* __restrict__ newe,
                           __half* __restrict__ nxtH,
                           float* __restrict__ out) {
    int n = (blockIdx.x * blockDim.x + threadIdx.x) >> 5;
    int lane = threadIdx.x & 31;
    if (n >= NN) return;
    int half = lane >> 4;
    int q    = lane & 15;
    unsigned hmask = half ? 0xFFFF0000u : 0x0000FFFFu;
    int b = d_rowptr[n], e = d_rowptr[n + 1];

    // h-side packed chunk: x = g-bytes, y = i-bytes
    uint2 hv = __ldg((const uint2*)(d_nrm8 + n * 2 * D) + q);

    float rsg = 0.f, rsi = 0.f;
    float4 accg = make_float4(0.f, 0.f, 0.f, 0.f);
    float4 acci = make_float4(0.f, 0.f, 0.f, 0.f);

    int i = b + half;
    for (; i + 2 < e; i += 4) {
        int t0 = __ldg(&d_csr_t[i]);
        int t1 = __ldg(&d_csr_t[i + 2]);
        uint2 v0 = __ldg((const uint2*)(d_nrm8 + t0 * 2 * D) + q);
        uint2 v1 = __ldg((const uint2*)(d_nrm8 + t1 * 2 * D) + q);
        uint2 e0 = __ldg((const uint2*)(curH + t0 * D) + q);
        uint2 e1 = __ldg((const uint2*)(curH + t1 * D) + q);

        int g0 = __dp4a((int)hv.x, (int)v0.x, 0);
        int i0 = __dp4a((int)hv.y, (int)v0.y, 0);
        int g1 = __dp4a((int)hv.x, (int)v1.x, 0);
        int i1 = __dp4a((int)hv.y, (int)v1.y, 0);

        #pragma unroll
        for (int o = 8; o >= 1; o >>= 1) {
            g0 += __shfl_xor_sync(hmask, g0, o);
            i0 += __shfl_xor_sync(hmask, i0, o);
            g1 += __shfl_xor_sync(hmask, g1, o);
            i1 += __shfl_xor_sync(hmask, i1, o);
        }
        float ag0 = fmaf((float)g0, KQ, 0.5f);
        float ai0 = fmaf((float)i0, KQ, 0.5f);
        float ag1 = fmaf((float)g1, KQ, 0.5f);
        float ai1 = fmaf((float)i1, KQ, 0.5f);
        rsg += ag0 + ag1;
        rsi += ai0 + ai1;
        float2 f0 = u2f2(e0.x), f1 = u2f2(e0.y);
        float2 f2 = u2f2(e1.x), f3 = u2f2(e1.y);
        accg.x += ag0 * f0.x + ag1 * f2.x;
        accg.y += ag0 * f0.y + ag1 * f2.y;
        accg.z += ag0 * f1.x + ag1 * f3.x;
        accg.w += ag0 * f1.y + ag1 * f3.y;
        acci.x += ai0 * f0.x + ai1 * f2.x;
        acci.y += ai0 * f0.y + ai1 * f2.y;
        acci.z += ai0 * f1.x + ai1 * f3.x;
        acci.w += ai0 * f1.y + ai1 * f3.y;
    }
    for (; i < e; i += 2) {
        int t0 = __ldg(&d_csr_t[i]);
        uint2 v0 = __ldg((const uint2*)(d_nrm8 + t0 * 2 * D) + q);
        uint2 e0 = __ldg((const uint2*)(curH + t0 * D) + q);
        int g0 = __dp4a((int)hv.x, (int)v0.x, 0);
        int i0 = __dp4a((int)hv.y, (int)v0.y, 0);
        #pragma unroll
        for (int o = 8; o >= 1; o >>= 1) {
            g0 += __shfl_xor_sync(hmask, g0, o);
            i0 += __shfl_xor_sync(hmask, i0, o);
        }
        float ag0 = fmaf((float)g0, KQ, 0.5f);
        float ai0 = fmaf((float)i0, KQ, 0.5f);
        rsg += ag0;
        rsi += ai0;
        float2 f0 = u2f2(e0.x), f1 = u2f2(e0.y);
        accg.x += ag0 * f0.x; accg.y += ag0 * f0.y;
        accg.z += ag0 * f1.x; accg.w += ag0 * f1.y;
        acci.x += ai0 * f0.x; acci.y += ai0 * f0.y;
        acci.z += ai0 * f1.x; acci.w += ai0 * f1.y;
    }

    // combine halves (warp reconverged)
    rsg += __shfl_xor_sync(0xffffffffu, rsg, 16);
    rsi += __shfl_xor_sync(0xffffffffu, rsi, 16);
    accg.x += __shfl_xor_sync(0xffffffffu, accg.x, 16);
    accg.y += __shfl_xor_sync(0xffffffffu, accg.y, 16);
    accg.z += __shfl_xor_sync(0xffffffffu, accg.z, 16);
    accg.w += __shfl_xor_sync(0xffffffffu, accg.w, 16);
    acci.x += __shfl_xor_sync(0xffffffffu, acci.x, 16);
    acci.y += __shfl_xor_sync(0xffffffffu, acci.y, 16);
    acci.z += __shfl_xor_sync(0xffffffffu, acci.z, 16);
    acci.w += __shfl_xor_sync(0xffffffffu, acci.w, 16);

    float dg = (rsg > 0.f) ? (1.0f / rsg) : 0.f;
    float di = (rsi > 0.f) ? (1.0f / rsi) : 0.f;

    if (half == 0) {
        float4 gh4 = __ldg((const float4*)(d_gnn + n * D) + q);
        float4 ih4 = __ldg((const float4*)(d_int + n * D) + q);
        float4 e0  = __ldg((const float4*)(cur   + n * D) + q);
        float4 nv;
        nv.x = gh4.x + ih4.x + dg * accg.x + di * acci.x + e0.x;
        nv.y = gh4.y + ih4.y + dg * accg.y + di * acci.y + e0.y;
        nv.z = gh4.z + ih4.z + dg * accg.z + di * acci.z + e0.z;
        nv.w = gh4.w + ih4.w + dg * accg.w + di * acci.w + e0.w;
        ((float4*)(newe + n * D))[q] = nv;
        float4 ov = ((float4*)(out + n * D))[q];
        ov.x += nv.x; ov.y += nv.y; ov.z += nv.z; ov.w += nv.w;
        ((float4*)(out + n * D))[q] = ov;
        // shadows for next layer: f32 scaled + fp16 emb (OTHER buffer)
        float ds = d_dis[n];
        float4 sv = make_float4(ds * nv.x, ds * nv.y, ds * nv.z, ds * nv.w);
        ((float4*)(d_scaled + n * D))[q] = sv;
        __half2 h0 = __floats2half2_rn(nv.x, nv.y);
        __half2 h1 = __floats2half2_rn(nv.z, nv.w);
        uint2 ue_;
        ue_.x = *(unsigned*)&h0; ue_.y = *(unsigned*)&h1;
        ((uint2*)(nxtH + n * D))[q] = ue_;
    }
}

// ---------------------------------------------------------------------------
extern "C" void kernel_launch(void* const* d_in, const int* in_sizes, int n_in,
                              void* d_out, int out_size) {
    const float* ue = (const float*)d_in[0];
    const float* ie = (const float*)d_in[1];
    const float* uW = (const float*)d_in[2];
    const float* iW = (const float*)d_in[3];
    const int*   h  = (const int*)d_in[4];
    const int*   t  = (const int*)d_in[5];
    float* out = (float*)d_out;

    const int TB = 256;
    const int n4   = NN * D / 4;
    const int gN4  = (n4 + TB - 1) / TB;
    const int gNN  = (NN + TB - 1) / TB;
    const int gE   = (NE + TB - 1) / TB;
    const int gNW  = (NN * 32 + TB - 1) / TB;   // warp-per-node

    float *embA, *embB;
    __half *embHA, *embHB;
    cudaGetSymbolAddress((void**)&embA, d_embA);
    cudaGetSymbolAddress((void**)&embB, d_embB);
    cudaGetSymbolAddress((void**)&embHA, d_embHA);
    cudaGetSymbolAddress((void**)&embHB, d_embHB);

    k_init<<<gN4, TB>>>(ue, ie, out);
    k_cnt_zero<<<gNN, TB>>>();
    k_cnt<<<gE, TB>>>(h);
    k_blocksum<<<NBLK, SCAN_TB>>>();
    k_scanblk<<<1, 1024>>>();
    k_rowptr<<<NBLK, SCAN_TB>>>();
    k_csr<<<gE, TB>>>(h, t);
    k_scale0<<<gN4, TB>>>();

    float* cur = embA;  float* nxt = embB;
    __half* curH = embHA; __half* nxtH = embHB;
    for (int layer = 0; layer < NL; layer++) {
        k_spmm_gnn<<<gNW, TB>>>();
        k_intent<<<NN / 8, TB>>>(cur, uW, iW);
        k_adaptive<<<gNW, TB>>>(cur, curH, nxt, nxtH, out);
        float* tf = cur; cur = nxt; nxt = tf;
        __half* th = curH; curH = nxtH; nxtH = th;
    }
}

// round 14
// speedup vs baseline: 1.1560x; 1.0115x over previous
#include <cuda_runtime.h>
#include <cuda_fp16.h>
#include <math.h>

#define NU 50000
#define NI 100000
#define NN 150000
#define D  64
#define NINT 128
#define NE 3000000
#define NL 2
#define SCAN_TB 256
#define NBLK ((NN + SCAN_TB - 1) / SCAN_TB)   // 586

// alpha scale: dot_int/(127*127) -> alpha = (dot+1)/2 = dot_int*K + 0.5
#define KQ (0.5f / 16129.0f)

// ---------------- scratch (device globals) ----------------------------------
__device__ __align__(256) float d_embA[NN * D];
__device__ __align__(256) float d_embB[NN * D];
__device__ __align__(256) float d_gnn[NN * D];
__device__ __align__(256) float d_int[NN * D];
__device__ __align__(256) __half d_scaledH[NN * D];  // fp16(dis[n]*emb[n])
__device__ __align__(256) __half d_embHA[NN * D];    // fp16 emb shadow (dbl-buffered)
__device__ __align__(256) __half d_embHB[NN * D];
// int8 packed normalized rows: 128B/node; chunk q (8B) = { g[4q..4q+3], i[4q..4q+3] }
__device__ __align__(256) char d_nrm8[NN * 2 * D];
__device__ __align__(256) float d_dis[NN];
__device__ __align__(256) int   d_cnt[NN];
__device__ __align__(256) int   d_rowptr[NN + 1];
__device__ __align__(256) int   d_fill[NN];
__device__ __align__(256) int   d_csr_t[NE];
__device__ __align__(256) int   d_blksum[NBLK];

__device__ __forceinline__ float2 u2f2(unsigned u) {
    return __half22float2(*(__half2*)&u);
}
__device__ __forceinline__ unsigned pack_q127(float a, float b, float c, float d, float s) {
    int b0 = max(-127, min(127, __float2int_rn(a * s)));
    int b1 = max(-127, min(127, __float2int_rn(b * s)));
    int b2 = max(-127, min(127, __float2int_rn(c * s)));
    int b3 = max(-127, min(127, __float2int_rn(d * s)));
    return (unsigned)(b0 & 0xFF) | ((unsigned)(b1 & 0xFF) << 8) |
           ((unsigned)(b2 & 0xFF) << 16) | ((unsigned)(b3 & 0xFF) << 24);
}

// ---------------------------------------------------------------------------
__global__ void k_init(const float* __restrict__ ue, const float* __restrict__ ie,
                       float* __restrict__ out) {
    int i = blockIdx.x * blockDim.x + threadIdx.x;
    const int n4  = NN * D / 4;
    const int nu4 = NU * D / 4;
    if (i >= n4) return;
    float4 v = (i < nu4) ? ((const float4*)ue)[i] : ((const float4*)ie)[i - nu4];
    ((float4*)d_embA)[i] = v;
    ((float4*)out)[i]    = v;
}

__global__ void k_cnt_zero() {
    int i = blockIdx.x * blockDim.x + threadIdx.x;
    if (i < NN) d_cnt[i] = 0;
}

__global__ void k_cnt(const int* __restrict__ h) {
    int e = blockIdx.x * blockDim.x + threadIdx.x;
    if (e < NE) atomicAdd(&d_cnt[h[e]], 1);
}

__global__ void k_blocksum() {
    __shared__ int sh[SCAN_TB];
    int i = blockIdx.x * SCAN_TB + threadIdx.x;
    int v = (i < NN) ? d_cnt[i] : 0;
    sh[threadIdx.x] = v;
    __syncthreads();
    for (int off = SCAN_TB / 2; off > 0; off >>= 1) {
        if (threadIdx.x < off) sh[threadIdx.x] += sh[threadIdx.x + off];
        __syncthreads();
    }
    if (threadIdx.x == 0) d_blksum[blockIdx.x] = sh[0];
}

__global__ void k_scanblk() {
    __shared__ int sh[1024];
    int tid = threadIdx.x;
    sh[tid] = (tid < NBLK) ? d_blksum[tid] : 0;
    __syncthreads();
    for (int off = 1; off < 1024; off <<= 1) {
        int v = (tid >= off) ? sh[tid - off] : 0;
        __syncthreads();
        sh[tid] += v;
        __syncthreads();
    }
    if (tid < NBLK) d_blksum[tid] = (tid > 0) ? sh[tid - 1] : 0;
    if (tid == 0) d_rowptr[NN] = sh[1023];
}

__global__ void k_rowptr() {
    __shared__ int sh[SCAN_TB];
    int i = blockIdx.x * SCAN_TB + threadIdx.x;
    int c = (i < NN) ? d_cnt[i] : 0;
    sh[threadIdx.x] = c;
    __syncthreads();
    for (int off = 1; off < SCAN_TB; off <<= 1) {
        int v = (threadIdx.x >= off) ? sh[threadIdx.x - off] : 0;
        __syncthreads();
        sh[threadIdx.x] += v;
        __syncthreads();
    }
    if (i < NN) {
        int excl = sh[threadIdx.x] - c + d_blksum[blockIdx.x];
        d_rowptr[i] = excl;
        d_dis[i]  = (c > 0) ? rsqrtf((float)c) : 0.0f;
        d_fill[i] = 0;
    }
}

__global__ void k_csr(const int* __restrict__ h, const int* __restrict__ t) {
    int e = blockIdx.x * blockDim.x + threadIdx.x;
    if (e >= NE) return;
    int hh = h[e];
    int pos = d_rowptr[hh] + atomicAdd(&d_fill[hh], 1);
    d_csr_t[pos] = t[e];
}

// scaledH = fp16(dis[n]*embA), embHA = fp16(embA)  (layer-0 shadows)
__global__ void k_scale0() {
    int i = blockIdx.x * blockDim.x + threadIdx.x;
    const int n4 = NN * D / 4;
    if (i >= n4) return;
    float s = d_dis[i >> 4];
    float4 v = ((const float4*)d_embA)[i];
    __half2 h0 = __floats2half2_rn(v.x, v.y);
    __half2 h1 = __floats2half2_rn(v.z, v.w);
    uint2 ue_;
    ue_.x = *(unsigned*)&h0; ue_.y = *(unsigned*)&h1;
    ((uint2*)d_embHA)[i] = ue_;
    __half2 s0 = __floats2half2_rn(s * v.x, s * v.y);
    __half2 s1 = __floats2half2_rn(s * v.z, s * v.w);
    uint2 us_;
    us_.x = *(unsigned*)&s0; us_.y = *(unsigned*)&s1;
    ((uint2*)d_scaledH)[i] = us_;
}

// warp per node, 16 lanes/edge, 2 edges per half-iter (4 edges in flight).
// gnn[n] = dis[n] * sum_t scaledH[t] ; writes f32 row + int8 normalized g-part.
__global__ void k_spmm_gnn() {
    int n = (blockIdx.x * blockDim.x + threadIdx.x) >> 5;
    int lane = threadIdx.x & 31;
    if (n >= NN) return;
    int half = lane >> 4;
    int q    = lane & 15;
    float dh = d_dis[n];
    float4 a0 = make_float4(0.f, 0.f, 0.f, 0.f);
    float4 a1 = make_float4(0.f, 0.f, 0.f, 0.f);
    int b = d_rowptr[n], e = d_rowptr[n + 1];
    int i = b + half;
    for (; i + 2 < e; i += 4) {
        int t0 = __ldg(&d_csr_t[i]);
        int t1 = __ldg(&d_csr_t[i + 2]);
        uint2 r0 = __ldg((const uint2*)(d_scaledH + t0 * D) + q);
        uint2 r1 = __ldg((const uint2*)(d_scaledH + t1 * D) + q);
        float2 f;
        f = u2f2(r0.x); a0.x += f.x; a0.y += f.y;
        f = u2f2(r0.y); a0.z += f.x; a0.w += f.y;
        f = u2f2(r1.x); a1.x += f.x; a1.y += f.y;
        f = u2f2(r1.y); a1.z += f.x; a1.w += f.y;
    }
    for (; i < e; i += 2) {
        int t0 = __ldg(&d_csr_t[i]);
        uint2 r0 = __ldg((const uint2*)(d_scaledH + t0 * D) + q);
        float2 f;
        f = u2f2(r0.x); a0.x += f.x; a0.y += f.y;
        f = u2f2(r0.y); a0.z += f.x; a0.w += f.y;
    }
    a0.x = dh * (a0.x + a1.x); a0.y = dh * (a0.y + a1.y);
    a0.z = dh * (a0.z + a1.z); a0.w = dh * (a0.w + a1.w);
    a0.x += __shfl_xor_sync(0xffffffffu, a0.x, 16);
    a0.y += __shfl_xor_sync(0xffffffffu, a0.y, 16);
    a0.z += __shfl_xor_sync(0xffffffffu, a0.z, 16);
    a0.w += __shfl_xor_sync(0xffffffffu, a0.w, 16);
    float sg = a0.x * a0.x + a0.y * a0.y + a0.z * a0.z + a0.w * a0.w;
    #pragma unroll
    for (int o = 8; o >= 1; o >>= 1) sg += __shfl_xor_sync(0xffffffffu, sg, o);
    float s = 127.0f / fmaxf(sqrtf(sg), 1e-8f);
    if (half == 0) {
        ((float4*)(d_gnn + n * D))[q] = a0;
        // int8 g-part of chunk q (4 bytes at row offset 8q)
        unsigned p = pack_q127(a0.x, a0.y, a0.z, a0.w, s);
        *(unsigned*)(d_nrm8 + n * 2 * D + 8 * q) = p;
    }
}

// warp-per-row softmax-intent projection; writes f32 row + int8 normalized i-part.
__global__ void k_intent(const float* __restrict__ cur,
                         const float* __restrict__ uW, const float* __restrict__ iW) {
    __shared__ float WT[NINT][D + 1];
    __shared__ float rowbuf[8][D];
    int wid = threadIdx.x >> 5, lane = threadIdx.x & 31;
    int row0 = blockIdx.x * 8;
    const float* W = (row0 < NU) ? uW : iW;
    for (int idx = threadIdx.x; idx < D * NINT; idx += blockDim.x) {
        int dd = idx / NINT, j = idx % NINT;
        WT[j][dd] = W[idx];
    }
    __syncthreads();
    int row = row0 + wid;
    if (row >= NN) return;
    const float* src = cur + row * D;
    rowbuf[wid][lane]      = src[lane];
    rowbuf[wid][lane + 32] = src[lane + 32];
    __syncwarp();

    float lg[4] = {0.f, 0.f, 0.f, 0.f};
    #pragma unroll
    for (int dd = 0; dd < D; dd++) {
        float rb = rowbuf[wid][dd];
        #pragma unroll
        for (int s = 0; s < 4; s++) lg[s] += rb * WT[s * 32 + lane][dd];
    }
    float m = fmaxf(fmaxf(lg[0], lg[1]), fmaxf(lg[2], lg[3]));
    #pragma unroll
    for (int o = 16; o >= 1; o >>= 1) m = fmaxf(m, __shfl_xor_sync(0xffffffffu, m, o));
    float p[4], ssum = 0.f;
    #pragma unroll
    for (int s = 0; s < 4; s++) { p[s] = expf(lg[s] - m); ssum += p[s]; }
    #pragma unroll
    for (int o = 16; o >= 1; o >>= 1) ssum += __shfl_xor_sync(0xffffffffu, ssum, o);
    float inv = 1.0f / ssum;
    #pragma unroll
    for (int s = 0; s < 4; s++) p[s] *= inv;

    float o0 = 0.f, o1 = 0.f;
    #pragma unroll
    for (int s = 0; s < 4; s++) {
        #pragma unroll
        for (int l = 0; l < 32; l++) {
            float pv = __shfl_sync(0xffffffffu, p[s], l);
            int j = s * 32 + l;
            o0 += pv * WT[j][lane];
            o1 += pv * WT[j][lane + 32];
        }
    }
    d_int[row * D + lane]      = o0;
    d_int[row * D + lane + 32] = o1;
    float si = o0 * o0 + o1 * o1;
    #pragma unroll
    for (int o = 16; o >= 1; o >>= 1) si += __shfl_xor_sync(0xffffffffu, si, o);
    float s = 127.0f / fmaxf(sqrtf(si), 1e-8f);
    // int8 i-part: dim d -> byte n*128 + 8*(d/4) + 4 + (d%4)
    int d0 = lane, d1 = lane + 32;
    int q0 = max(-127, min(127, __float2int_rn(o0 * s)));
    int q1 = max(-127, min(127, __float2int_rn(o1 * s)));
    d_nrm8[row * 2 * D + 8 * (d0 >> 2) + 4 + (d0 & 3)] = (char)q0;
    d_nrm8[row * 2 * D + 8 * (d1 >> 2) + 4 + (d1 & 3)] = (char)q1;
}

// fused adaptive pass, warp per node, 16 lanes/edge, unrolled 2x per half.
// Per edge-lane: ONE 8B int8 load (both dots via dp4a) + ONE 8B fp16 emb load.
__global__ void k_adaptive(const float* __restrict__ cur,
                           const __half* __restrict__ curH,
                           float* __restrict__ newe,
                           __half* __restrict__ nxtH,
                           float* __restrict__ out) {
    int n = (blockIdx.x * blockDim.x + threadIdx.x) >> 5;
    int lane = threadIdx.x & 31;
    if (n >= NN) return;
    int half = lane >> 4;
    int q    = lane & 15;
    unsigned hmask = half ? 0xFFFF0000u : 0x0000FFFFu;
    int b = d_rowptr[n], e = d_rowptr[n + 1];

    // h-side packed chunk: x = g-bytes, y = i-bytes
    uint2 hv = __ldg((const uint2*)(d_nrm8 + n * 2 * D) + q);

    float rsg = 0.f, rsi = 0.f;
    float4 accg = make_float4(0.f, 0.f, 0.f, 0.f);
    float4 acci = make_float4(0.f, 0.f, 0.f, 0.f);

    int i = b + half;
    for (; i + 2 < e; i += 4) {
        int t0 = __ldg(&d_csr_t[i]);
        int t1 = __ldg(&d_csr_t[i + 2]);
        uint2 v0 = __ldg((const uint2*)(d_nrm8 + t0 * 2 * D) + q);
        uint2 v1 = __ldg((const uint2*)(d_nrm8 + t1 * 2 * D) + q);
        uint2 e0 = __ldg((const uint2*)(curH + t0 * D) + q);
        uint2 e1 = __ldg((const uint2*)(curH + t1 * D) + q);

        int g0 = __dp4a((int)hv.x, (int)v0.x, 0);
        int i0 = __dp4a((int)hv.y, (int)v0.y, 0);
        int g1 = __dp4a((int)hv.x, (int)v1.x, 0);
        int i1 = __dp4a((int)hv.y, (int)v1.y, 0);

        #pragma unroll
        for (int o = 8; o >= 1; o >>= 1) {
            g0 += __shfl_xor_sync(hmask, g0, o);
            i0 += __shfl_xor_sync(hmask, i0, o);
            g1 += __shfl_xor_sync(hmask, g1, o);
            i1 += __shfl_xor_sync(hmask, i1, o);
        }
        float ag0 = fmaf((float)g0, KQ, 0.5f);
        float ai0 = fmaf((float)i0, KQ, 0.5f);
        float ag1 = fmaf((float)g1, KQ, 0.5f);
        float ai1 = fmaf((float)i1, KQ, 0.5f);
        rsg += ag0 + ag1;
        rsi += ai0 + ai1;
        float2 f0 = u2f2(e0.x), f1 = u2f2(e0.y);
        float2 f2 = u2f2(e1.x), f3 = u2f2(e1.y);
        accg.x += ag0 * f0.x + ag1 * f2.x;
        accg.y += ag0 * f0.y + ag1 * f2.y;
        accg.z += ag0 * f1.x + ag1 * f3.x;
        accg.w += ag0 * f1.y + ag1 * f3.y;
        acci.x += ai0 * f0.x + ai1 * f2.x;
        acci.y += ai0 * f0.y + ai1 * f2.y;
        acci.z += ai0 * f1.x + ai1 * f3.x;
        acci.w += ai0 * f1.y + ai1 * f3.y;
    }
    for (; i < e; i += 2) {
        int t0 = __ldg(&d_csr_t[i]);
        uint2 v0 = __ldg((const uint2*)(d_nrm8 + t0 * 2 * D) + q);
        uint2 e0 = __ldg((const uint2*)(curH + t0 * D) + q);
        int g0 = __dp4a((int)hv.x, (int)v0.x, 0);
        int i0 = __dp4a((int)hv.y, (int)v0.y, 0);
        #pragma unroll
        for (int o = 8; o >= 1; o >>= 1) {
            g0 += __shfl_xor_sync(hmask, g0, o);
            i0 += __shfl_xor_sync(hmask, i0, o);
        }
        float ag0 = fmaf((float)g0, KQ, 0.5f);
        float ai0 = fmaf((float)i0, KQ, 0.5f);
        rsg += ag0;
        rsi += ai0;
        float2 f0 = u2f2(e0.x), f1 = u2f2(e0.y);
        accg.x += ag0 * f0.x; accg.y += ag0 * f0.y;
        accg.z += ag0 * f1.x; accg.w += ag0 * f1.y;
        acci.x += ai0 * f0.x; acci.y += ai0 * f0.y;
        acci.z += ai0 * f1.x; acci.w += ai0 * f1.y;
    }

    // combine halves (warp reconverged)
    rsg += __shfl_xor_sync(0xffffffffu, rsg, 16);
    rsi += __shfl_xor_sync(0xffffffffu, rsi, 16);
    accg.x += __shfl_xor_sync(0xffffffffu, accg.x, 16);
    accg.y += __shfl_xor_sync(0xffffffffu, accg.y, 16);
    accg.z += __shfl_xor_sync(0xffffffffu, accg.z, 16);
    accg.w += __shfl_xor_sync(0xffffffffu, accg.w, 16);
    acci.x += __shfl_xor_sync(0xffffffffu, acci.x, 16);
    acci.y += __shfl_xor_sync(0xffffffffu, acci.y, 16);
    acci.z += __shfl_xor_sync(0xffffffffu, acci.z, 16);
    acci.w += __shfl_xor_sync(0xffffffffu, acci.w, 16);

    float dg = (rsg > 0.f) ? (1.0f / rsg) : 0.f;
    float di = (rsi > 0.f) ? (1.0f / rsi) : 0.f;

    if (half == 0) {
        float4 gh4 = __ldg((const float4*)(d_gnn + n * D) + q);
        float4 ih4 = __ldg((const float4*)(d_int + n * D) + q);
        float4 e0  = __ldg((const float4*)(cur   + n * D) + q);
        float4 nv;
        nv.x = gh4.x + ih4.x + dg * accg.x + di * acci.x + e0.x;
        nv.y = gh4.y + ih4.y + dg * accg.y + di * acci.y + e0.y;
        nv.z = gh4.z + ih4.z + dg * accg.z + di * acci.z + e0.z;
        nv.w = gh4.w + ih4.w + dg * accg.w + di * acci.w + e0.w;
        ((float4*)(newe + n * D))[q] = nv;
        float4 ov = ((float4*)(out + n * D))[q];
        ov.x += nv.x; ov.y += nv.y; ov.z += nv.z; ov.w += nv.w;
        ((float4*)(out + n * D))[q] = ov;
        // shadows for next layer: fp16 scaled + fp16 emb (OTHER buffer)
        float ds = d_dis[n];
        __half2 s0 = __floats2half2_rn(ds * nv.x, ds * nv.y);
        __half2 s1 = __floats2half2_rn(ds * nv.z, ds * nv.w);
        uint2 us_;
        us_.x = *(unsigned*)&s0; us_.y = *(unsigned*)&s1;
        ((uint2*)(d_scaledH + n * D))[q] = us_;
        __half2 h0 = __floats2half2_rn(nv.x, nv.y);
        __half2 h1 = __floats2half2_rn(nv.z, nv.w);
        uint2 ue_;
        ue_.x = *(unsigned*)&h0; ue_.y = *(unsigned*)&h1;
        ((uint2*)(nxtH + n * D))[q] = ue_;
    }
}

// ---------------------------------------------------------------------------
extern "C" void kernel_launch(void* const* d_in, const int* in_sizes, int n_in,
                              void* d_out, int out_size) {
    const float* ue = (const float*)d_in[0];
    const float* ie = (const float*)d_in[1];
    const float* uW = (const float*)d_in[2];
    const float* iW = (const float*)d_in[3];
    const int*   h  = (const int*)d_in[4];
    const int*   t  = (const int*)d_in[5];
    float* out = (float*)d_out;

    const int TB = 256;
    const int n4   = NN * D / 4;
    const int gN4  = (n4 + TB - 1) / TB;
    const int gNN  = (NN + TB - 1) / TB;
    const int gE   = (NE + TB - 1) / TB;
    const int gNW  = (NN * 32 + TB - 1) / TB;   // warp-per-node

    float *embA, *embB;
    __half *embHA, *embHB;
    cudaGetSymbolAddress((void**)&embA, d_embA);
    cudaGetSymbolAddress((void**)&embB, d_embB);
    cudaGetSymbolAddress((void**)&embHA, d_embHA);
    cudaGetSymbolAddress((void**)&embHB, d_embHB);

    k_init<<<gN4, TB>>>(ue, ie, out);
    k_cnt_zero<<<gNN, TB>>>();
    k_cnt<<<gE, TB>>>(h);
    k_blocksum<<<NBLK, SCAN_TB>>>();
    k_scanblk<<<1, 1024>>>();
    k_rowptr<<<NBLK, SCAN_TB>>>();
    k_csr<<<gE, TB>>>(h, t);
    k_scale0<<<gN4, TB>>>();

    float* cur = embA;  float* nxt = embB;
    __half* curH = embHA; __half* nxtH = embHB;
    for (int layer = 0; layer < NL; layer++) {
        k_spmm_gnn<<<gNW, TB>>>();
        k_intent<<<NN / 8, TB>>>(cur, uW, iW);
        k_adaptive<<<gNW, TB>>>(cur, curH, nxt, nxtH, out);
        float* tf = cur; cur = nxt; nxt = tf;
        __half* th = curH; curH = nxtH; nxtH = th;
    }
}